// round 10
// baseline (speedup 1.0000x reference)
#include <cuda_runtime.h>

#define N_MAX     1048576
#define SEGS      (64 * 4096)   // 262144 segments
#define GRID_DIM  64
#define NUM_CELLS 4096
#define PREP_BLOCKS 256
#define CPB       32            // cells per gather block
#define STAGE_MAX 512           // staged pids per gather block
#define IDX_BITS  18            // SEGS = 2^18

// ---- scratch (static device globals; zero-initialized at module load) ----
__device__ int g_idx[N_MAX];           // packed: cell idx | rank<<18
__device__ int g_pids[N_MAX];          // point ids sorted by cell
__device__ int g_counts[SEGS];         // points per cell (re-zeroed in scan phase)
__device__ int g_offsets[SEGS + 1];    // exclusive prefix + sentinel
__device__ int g_blocksums[PREP_BLOCKS];
__device__ int g_prefix[PREP_BLOCKS];  // exclusive scan of block totals
// sync state (all reset by k_gather block 0 for the next graph replay)
__device__ int g_d1, g_f1;             // hist -> scan
__device__ int g_d2, g_f2;             // scan publish
__device__ int g_d3, g_f3;             // scan -> scatter

// single-hop grid barrier: all blocks must be co-resident.
__device__ __forceinline__ void grid_sync(int* done, int* flag) {
    __syncthreads();
    if (threadIdx.x == 0) {
        __threadfence();
        int t = atomicAdd(done, 1);
        if (t == PREP_BLOCKS - 1) {
            atomicExch(flag, 1);
        } else {
            while (atomicAdd(flag, 0) == 0) { __nanosleep(64); }
        }
        __threadfence();
    }
    __syncthreads();
}

// ---------------------------------------------------------------
// Fused hist -> scan -> scatter. 256 blocks x 1024 threads, all co-resident.
// pos/batch are int32 (JAX x64 disabled => int64 request materializes int32).
__global__ void __launch_bounds__(1024) k_prep(const int2* __restrict__ pos,
                                               const int* __restrict__ batch,
                                               int n) {
    int gtid = blockIdx.x * 1024 + threadIdx.x;   // 0..262143

    // ---- Phase A: histogram + packed idx|rank ----
    #pragma unroll
    for (int k = 0; k < 4; k++) {
        int i = gtid + k * (PREP_BLOCKS * 1024);
        if (i < n) {
            int2 p = pos[i];
            int idx = batch[i] * NUM_CELLS
                    + (p.x >> 2) * GRID_DIM
                    + (p.y >> 2);
            int rank = atomicAdd(&g_counts[idx], 1);
            g_idx[i] = idx | (rank << IDX_BITS);
        }
    }
    grid_sync(&g_d1, &g_f1);

    // ---- Phase B: exclusive scan of counts (single-hop publish) ----
    {
        int bid  = blockIdx.x;
        int i    = gtid;
        int lane = threadIdx.x & 31;
        int wid  = threadIdx.x >> 5;

        int v = g_counts[i];
        g_counts[i] = 0;                       // reset for next replay

        int incl = v;
        #pragma unroll
        for (int d = 1; d < 32; d <<= 1) {
            int u = __shfl_up_sync(0xffffffffu, incl, d);
            if (lane >= d) incl += u;
        }
        __shared__ int ws[32];
        __shared__ int wexcl[32];
        __shared__ int s_last;
        __shared__ int s_base;
        if (lane == 31) ws[wid] = incl;
        __syncthreads();
        if (wid == 0) {
            int w  = ws[lane];
            int wi = w;
            #pragma unroll
            for (int d = 1; d < 32; d <<= 1) {
                int u = __shfl_up_sync(0xffffffffu, wi, d);
                if (lane >= d) wi += u;
            }
            wexcl[lane] = wi - w;
            if (lane == 31) {
                g_blocksums[bid] = wi;         // block total
                __threadfence();
                int t = atomicAdd(&g_d2, 1);
                s_last = (t == PREP_BLOCKS - 1);
            }
        }
        __syncthreads();

        if (s_last) {                          // block-uniform branch
            __shared__ int ws2[8];
            int t = threadIdx.x;
            int bv = 0, bi = 0;
            if (t < PREP_BLOCKS) {
                bv = g_blocksums[t];
                bi = bv;
                #pragma unroll
                for (int d = 1; d < 32; d <<= 1) {
                    int u = __shfl_up_sync(0xffffffffu, bi, d);
                    if ((t & 31) >= d) bi += u;
                }
                if ((t & 31) == 31) ws2[t >> 5] = bi;
            }
            __syncthreads();
            if (t < PREP_BLOCKS) {
                int add = 0;
                #pragma unroll
                for (int wq = 0; wq < 8; wq++)
                    if (wq < (t >> 5)) add += ws2[wq];
                g_prefix[t] = bi - bv + add;   // exclusive base for block t
            }
            __syncthreads();
            if (t == 0) {
                __threadfence();
                atomicExch(&g_f2, 1);          // publish
            }
        }

        if (threadIdx.x == 0) {                // single-hop wait
            while (atomicAdd(&g_f2, 0) == 0) { __nanosleep(64); }
            __threadfence();
            s_base = g_prefix[bid];
        }
        __syncthreads();

        g_offsets[i] = incl - v + wexcl[wid] + s_base;
        if (bid == PREP_BLOCKS - 1 && threadIdx.x == 1023)
            g_offsets[SEGS] = n;               // sentinel
    }
    grid_sync(&g_d3, &g_f3);                   // all offsets visible

    // ---- Phase C: atomic-free scatter ----
    #pragma unroll
    for (int k = 0; k < 4; k++) {
        int i = gtid + k * (PREP_BLOCKS * 1024);
        if (i < n) {
            int packed = g_idx[i];
            int idx  = packed & (SEGS - 1);
            int rank = ((unsigned)packed) >> IDX_BITS;
            g_pids[g_offsets[idx] + rank] = i;
        }
    }
}

// ---------------------------------------------------------------
// Gather: block = 32 contiguous cells; pids staged in smem. Half-warp
// partitioning (lanes 0-15: cells cA,cA+1; lanes 16-31: cA+2,cA+3); each lane
// = one float4 column, 16 lanes = full 256B row.
// BRANCH-FREE inner loop: point index clamped to min(j, cnt-1) and loaded
// unconditionally -> ptxas can software-pipeline loads across iterations
// (duplicate max is a no-op; empty-cell garbage is masked in-bounds and the
// accumulator is discarded at the end; fmaxf drops NaN garbage).
__global__ void __launch_bounds__(256, 6)
k_gather(const float4* __restrict__ x4, float4* __restrict__ out4) {
    if (blockIdx.x == 0 && threadIdx.x == 0) {
        g_d1 = 0; g_f1 = 0; g_d2 = 0; g_f2 = 0; g_d3 = 0; g_f3 = 0;
    }

    __shared__ int s_off[CPB + 1];
    __shared__ int s_pid[STAGE_MAX];

    int tid   = threadIdx.x;
    int cbase = blockIdx.x * CPB;

    if (tid < CPB + 1)
        s_off[tid] = g_offsets[cbase + tid];
    __syncthreads();

    int base0 = s_off[0];
    int total = s_off[CPB] - base0;
    bool all_staged = (total <= STAGE_MAX);
    int stage = all_staged ? total : 0;
    for (int i = tid; i < stage; i += 256)
        s_pid[i] = g_pids[base0 + i];
    __syncthreads();

    int warp = tid >> 5;
    int lane = tid & 31;
    int g    = lane >> 4;        // half-warp id (0/1)
    int s    = lane & 15;        // float4 column within 64-ch row
    int cA   = warp * 4 + g * 2;
    int cB   = cA + 1;

    int offA = s_off[cA],  offB = s_off[cB];
    int cntA = s_off[cA + 1] - offA;
    int cntB = s_off[cB + 1] - offB;
    int lsA  = offA - base0,  lsB = offB - base0;

    int jm = cntA > cntB ? cntA : cntB;       // half-warp max (divergence OK)
    int mA = cntA > 0 ? cntA - 1 : 0;         // clamp targets
    int mB = cntB > 0 ? cntB - 1 : 0;

    const float ninf = __int_as_float(0xff800000);
    float4 accA = make_float4(ninf, ninf, ninf, ninf);
    float4 accB = make_float4(ninf, ninf, ninf, ninf);

    if (all_staged) {
        #pragma unroll 2
        for (int j = 0; j < jm; j++) {
            int jA = j < mA ? j : mA;
            int jB = j < mB ? j : mB;
            int pA = s_pid[lsA + jA] & (N_MAX - 1);
            int pB = s_pid[lsB + jB] & (N_MAX - 1);
            float4 vA = x4[pA * 16 + s];
            float4 vB = x4[pB * 16 + s];
            accA.x = fmaxf(accA.x, vA.x);
            accA.y = fmaxf(accA.y, vA.y);
            accA.z = fmaxf(accA.z, vA.z);
            accA.w = fmaxf(accA.w, vA.w);
            accB.x = fmaxf(accB.x, vB.x);
            accB.y = fmaxf(accB.y, vB.y);
            accB.z = fmaxf(accB.z, vB.z);
            accB.w = fmaxf(accB.w, vB.w);
        }
    } else {
        #pragma unroll 2
        for (int j = 0; j < jm; j++) {
            int jA = j < mA ? j : mA;
            int jB = j < mB ? j : mB;
            int pA = g_pids[base0 + lsA + jA] & (N_MAX - 1);
            int pB = g_pids[base0 + lsB + jB] & (N_MAX - 1);
            float4 vA = x4[pA * 16 + s];
            float4 vB = x4[pB * 16 + s];
            accA.x = fmaxf(accA.x, vA.x);
            accA.y = fmaxf(accA.y, vA.y);
            accA.z = fmaxf(accA.z, vA.z);
            accA.w = fmaxf(accA.w, vA.w);
            accB.x = fmaxf(accB.x, vB.x);
            accB.y = fmaxf(accB.y, vB.y);
            accB.z = fmaxf(accB.z, vB.z);
            accB.w = fmaxf(accB.w, vB.w);
        }
    }

    if (cntA == 0) accA = make_float4(0.f, 0.f, 0.f, 0.f);
    if (cntB == 0) accB = make_float4(0.f, 0.f, 0.f, 0.f);
    out4[(cbase + cA) * 16 + s] = accA;   // 16 lanes -> full 256B row
    out4[(cbase + cB) * 16 + s] = accB;
}

// ---------------------------------------------------------------
extern "C" void kernel_launch(void* const* d_in, const int* in_sizes, int n_in,
                              void* d_out, int out_size) {
    const float* x     = (const float*)d_in[0];
    const int2*  pos   = (const int2*)d_in[1];
    const int*   batch = (const int*)d_in[2];
    float* out = (float*)d_out;
    int n = in_sizes[2];     // number of points

    k_prep  <<<PREP_BLOCKS, 1024>>>(pos, batch, n);
    k_gather<<<SEGS / CPB, 256>>>((const float4*)x, (float4*)out);
}

// round 11
// speedup vs baseline: 1.0105x; 1.0105x over previous
#include <cuda_runtime.h>

#define N_MAX     1048576
#define SEGS      (64 * 4096)   // 262144 segments
#define GRID_DIM  64
#define NUM_CELLS 4096
#define CPB       32            // cells per gather block
#define CAP       24            // bucket slots per cell (P(count>24) ~ 1e-11)
#define OVF_MAX   4096          // overflow list capacity

// ---- scratch (static device globals; zero-initialized at module load) ----
__device__ int  g_counts[SEGS];        // points per cell (reset by k_gather)
__device__ int  g_bucket[SEGS * CAP];  // direct per-cell pid buckets (~25MB)
__device__ int2 g_ovf[OVF_MAX];        // rare overflow entries (idx, pid)
__device__ int  g_ovf_n;               // overflow count (reset by k_reset)

// ---------------------------------------------------------------
__global__ void k_reset() {
    if (threadIdx.x == 0) g_ovf_n = 0;
}

// pos/batch are int32 (JAX x64 disabled => int64 request materializes int32).
// Builds per-cell pid lists DIRECTLY: rank from atomicAdd indexes a fixed-cap
// bucket; ranks >= CAP go to a tiny overflow list (handled in gather).
__global__ void k_hist(const int2* __restrict__ pos,
                       const int* __restrict__ batch, int n) {
    int i = blockIdx.x * blockDim.x + threadIdx.x;
    if (i >= n) return;
    int2 p = pos[i];
    int idx = batch[i] * NUM_CELLS
            + (p.x >> 2) * GRID_DIM
            + (p.y >> 2);
    int rank = atomicAdd(&g_counts[idx], 1);
    if (rank < CAP) {
        g_bucket[idx * CAP + rank] = i;
    } else {
        int e = atomicAdd(&g_ovf_n, 1);
        if (e < OVF_MAX) g_ovf[e] = make_int2(idx, i);
    }
}

// Gather: block = 32 contiguous cells; bucket slots staged coalesced in smem.
// Half-warp partitioning (R8 winner): lanes 0-15 own cells (cA,cA+1), lanes
// 16-31 own (cA+2,cA+3); each lane = one float4 column, 16 lanes = a full
// 256B row; 4 independent rows in flight per warp iteration. Predicated inner
// loop (branch-free clamp variant measured SLOWER in R10 - do not reinstate).
// Also: folds in rare overflow entries, and resets its cells' counts.
__global__ void __launch_bounds__(256, 6)
k_gather(const float4* __restrict__ x4, float4* __restrict__ out4) {
    __shared__ int s_cnt[CPB];
    __shared__ int s_pid[CPB * CAP];
    __shared__ int s_ovf_n;

    int tid   = threadIdx.x;
    int cbase = blockIdx.x * CPB;

    if (tid < CPB) {
        int c = g_counts[cbase + tid];
        s_cnt[tid] = c < CAP ? c : CAP;        // 0 iff cell truly empty
        g_counts[cbase + tid] = 0;             // reset for next replay
    }
    if (tid == 0) {
        int e = g_ovf_n;
        s_ovf_n = e < OVF_MAX ? e : OVF_MAX;
    }
    for (int i = tid; i < CPB * CAP; i += 256) // coalesced 3KB stage
        s_pid[i] = g_bucket[cbase * CAP + i];
    __syncthreads();

    int warp = tid >> 5;
    int lane = tid & 31;
    int g    = lane >> 4;        // half-warp id (0/1)
    int s    = lane & 15;        // float4 column within 64-ch row
    int cA   = warp * 4 + g * 2; // this half-warp's first cell
    int cB   = cA + 1;

    int cntA = s_cnt[cA];
    int cntB = s_cnt[cB];
    int bA   = cA * CAP;
    int bB   = cB * CAP;
    int jm   = cntA > cntB ? cntA : cntB;      // half-warp max (divergence OK)

    const float ninf = __int_as_float(0xff800000);
    float4 accA = make_float4(ninf, ninf, ninf, ninf);
    float4 accB = make_float4(ninf, ninf, ninf, ninf);

    for (int j = 0; j < jm; j++) {
        if (j < cntA) {
            int pid = s_pid[bA + j];
            float4 v = x4[pid * 16 + s];
            accA.x = fmaxf(accA.x, v.x);
            accA.y = fmaxf(accA.y, v.y);
            accA.z = fmaxf(accA.z, v.z);
            accA.w = fmaxf(accA.w, v.w);
        }
        if (j < cntB) {
            int pid = s_pid[bB + j];
            float4 v = x4[pid * 16 + s];
            accB.x = fmaxf(accB.x, v.x);
            accB.y = fmaxf(accB.y, v.y);
            accB.z = fmaxf(accB.z, v.z);
            accB.w = fmaxf(accB.w, v.w);
        }
    }

    // fold rare overflow points (count >= CAP) into the owning accumulator
    for (int e = 0; e < s_ovf_n; e++) {
        int2 ov = g_ovf[e];                    // L2-broadcast read
        int c = ov.x - cbase;
        if (c >= 0 && c < CPB && (c >> 2) == warp && (((c & 3) >> 1) == g)) {
            float4 v = x4[ov.y * 16 + s];
            if ((c & 1) == 0) {
                accA.x = fmaxf(accA.x, v.x);
                accA.y = fmaxf(accA.y, v.y);
                accA.z = fmaxf(accA.z, v.z);
                accA.w = fmaxf(accA.w, v.w);
            } else {
                accB.x = fmaxf(accB.x, v.x);
                accB.y = fmaxf(accB.y, v.y);
                accB.z = fmaxf(accB.z, v.z);
                accB.w = fmaxf(accB.w, v.w);
            }
        }
    }

    if (cntA == 0) accA = make_float4(0.f, 0.f, 0.f, 0.f);
    if (cntB == 0) accB = make_float4(0.f, 0.f, 0.f, 0.f);
    out4[(cbase + cA) * 16 + s] = accA;        // 16 lanes -> full 256B row
    out4[(cbase + cB) * 16 + s] = accB;
}

// ---------------------------------------------------------------
extern "C" void kernel_launch(void* const* d_in, const int* in_sizes, int n_in,
                              void* d_out, int out_size) {
    const float* x     = (const float*)d_in[0];
    const int2*  pos   = (const int2*)d_in[1];
    const int*   batch = (const int*)d_in[2];
    float* out = (float*)d_out;
    int n = in_sizes[2];     // number of points

    k_reset <<<1, 32>>>();
    k_hist  <<<(n + 255) / 256, 256>>>(pos, batch, n);
    k_gather<<<SEGS / CPB, 256>>>((const float4*)x, (float4*)out);
}

// round 12
// speedup vs baseline: 1.0763x; 1.0651x over previous
#include <cuda_runtime.h>

#define N_MAX     1048576
#define SEGS      (64 * 4096)   // 262144 segments
#define GRID_DIM  64
#define NUM_CELLS 4096
#define PREP_BLOCKS 256
#define CPB       32            // cells per gather block
#define STAGE_MAX 512           // staged pids per gather block
#define IDX_BITS  18            // SEGS = 2^18

// ---- scratch (static device globals; zero-initialized at module load) ----
__device__ int g_idx[N_MAX];           // packed: cell idx | rank<<18
__device__ int g_pids[N_MAX];          // point ids sorted by cell
__device__ int g_counts[SEGS];         // points per cell (re-zeroed in scan phase)
__device__ int g_offsets[SEGS + 1];    // exclusive prefix + sentinel
__device__ int g_blocksums[PREP_BLOCKS];
__device__ int g_prefix[PREP_BLOCKS];  // exclusive scan of block totals
// sync state (reset by k_gather block 0 for the next graph replay)
__device__ int g_d2, g_f2;             // scan publish
__device__ int g_d3, g_f3;             // scan -> scatter

// single-hop grid barrier: all blocks must be co-resident.
__device__ __forceinline__ void grid_sync(int* done, int* flag) {
    __syncthreads();
    if (threadIdx.x == 0) {
        __threadfence();
        int t = atomicAdd(done, 1);
        if (t == PREP_BLOCKS - 1) {
            atomicExch(flag, 1);
        } else {
            while (atomicAdd(flag, 0) == 0) { __nanosleep(64); }
        }
        __threadfence();
    }
    __syncthreads();
}

// ---------------------------------------------------------------
// pos/batch are int32 (JAX x64 disabled => int64 request materializes int32).
// atomicAdd's return = this point's rank within its cell -> packed into g_idx
// so the scatter phase needs no atomics.
__global__ void k_hist(const int2* __restrict__ pos,
                       const int* __restrict__ batch, int n) {
    int i = blockIdx.x * blockDim.x + threadIdx.x;
    if (i >= n) return;
    int2 p = pos[i];
    int idx = batch[i] * NUM_CELLS
            + (p.x >> 2) * GRID_DIM
            + (p.y >> 2);
    int rank = atomicAdd(&g_counts[idx], 1);
    g_idx[i] = idx | (rank << IDX_BITS);
}

// Fused scan + scatter. 256 blocks x 1024 threads, all co-resident.
__global__ void __launch_bounds__(1024) k_prep2(int n) {
    int gtid = blockIdx.x * 1024 + threadIdx.x;   // 0..262143

    // ---- scan of counts (single-hop publish) ----
    {
        int bid  = blockIdx.x;
        int i    = gtid;
        int lane = threadIdx.x & 31;
        int wid  = threadIdx.x >> 5;

        int v = g_counts[i];
        g_counts[i] = 0;                       // reset for next replay

        int incl = v;
        #pragma unroll
        for (int d = 1; d < 32; d <<= 1) {
            int u = __shfl_up_sync(0xffffffffu, incl, d);
            if (lane >= d) incl += u;
        }
        __shared__ int ws[32];
        __shared__ int wexcl[32];
        __shared__ int s_last;
        __shared__ int s_base;
        if (lane == 31) ws[wid] = incl;
        __syncthreads();
        if (wid == 0) {
            int w  = ws[lane];
            int wi = w;
            #pragma unroll
            for (int d = 1; d < 32; d <<= 1) {
                int u = __shfl_up_sync(0xffffffffu, wi, d);
                if (lane >= d) wi += u;
            }
            wexcl[lane] = wi - w;
            if (lane == 31) {
                g_blocksums[bid] = wi;         // block total
                __threadfence();
                int t = atomicAdd(&g_d2, 1);
                s_last = (t == PREP_BLOCKS - 1);
            }
        }
        __syncthreads();

        if (s_last) {                          // block-uniform branch
            __shared__ int ws2[8];
            int t = threadIdx.x;
            int bv = 0, bi = 0;
            if (t < PREP_BLOCKS) {
                bv = g_blocksums[t];
                bi = bv;
                #pragma unroll
                for (int d = 1; d < 32; d <<= 1) {
                    int u = __shfl_up_sync(0xffffffffu, bi, d);
                    if ((t & 31) >= d) bi += u;
                }
                if ((t & 31) == 31) ws2[t >> 5] = bi;
            }
            __syncthreads();
            if (t < PREP_BLOCKS) {
                int add = 0;
                #pragma unroll
                for (int wq = 0; wq < 8; wq++)
                    if (wq < (t >> 5)) add += ws2[wq];
                g_prefix[t] = bi - bv + add;   // exclusive base for block t
            }
            __syncthreads();
            if (t == 0) {
                __threadfence();
                atomicExch(&g_f2, 1);          // publish
            }
        }

        if (threadIdx.x == 0) {                // single-hop wait
            while (atomicAdd(&g_f2, 0) == 0) { __nanosleep(64); }
            __threadfence();
            s_base = g_prefix[bid];
        }
        __syncthreads();

        g_offsets[i] = incl - v + wexcl[wid] + s_base;
        if (bid == PREP_BLOCKS - 1 && threadIdx.x == 1023)
            g_offsets[SEGS] = n;               // sentinel
    }
    grid_sync(&g_d3, &g_f3);                   // all offsets visible

    // ---- atomic-free scatter ----
    #pragma unroll
    for (int k = 0; k < 4; k++) {
        int i = gtid + k * (PREP_BLOCKS * 1024);
        if (i < n) {
            int packed = g_idx[i];
            int idx  = packed & (SEGS - 1);
            int rank = ((unsigned)packed) >> IDX_BITS;
            g_pids[g_offsets[idx] + rank] = i;
        }
    }
}

// ---------------------------------------------------------------
// Gather: block = 32 contiguous cells; pids staged in smem. Half-warp
// partitioning (lanes 0-15: cells cA,cA+1; lanes 16-31: cA+2,cA+3); each lane
// = one float4 column, 16 lanes = full 256B row.
// SPLIT LOOP: j < min(cntA,cntB) runs with BOTH loads unconditional (zero
// branches, zero duplicate traffic, unroll 2 -> 4 LDG.128 in flight), then
// short predicated remainders. (R10's clamp variant = extra traffic, slower;
// R8's fully-predicated variant = branch-serialized. This is the midpoint.)
__global__ void __launch_bounds__(256, 6)
k_gather(const float4* __restrict__ x4, float4* __restrict__ out4) {
    if (blockIdx.x == 0 && threadIdx.x == 0) {
        g_d2 = 0; g_f2 = 0; g_d3 = 0; g_f3 = 0;
    }

    __shared__ int s_off[CPB + 1];
    __shared__ int s_pid[STAGE_MAX];

    int tid   = threadIdx.x;
    int cbase = blockIdx.x * CPB;

    if (tid < CPB + 1)
        s_off[tid] = g_offsets[cbase + tid];
    __syncthreads();

    int base0 = s_off[0];
    int total = s_off[CPB] - base0;
    bool all_staged = (total <= STAGE_MAX);
    int stage = all_staged ? total : 0;
    for (int i = tid; i < stage; i += 256)
        s_pid[i] = g_pids[base0 + i];
    __syncthreads();

    int warp = tid >> 5;
    int lane = tid & 31;
    int g    = lane >> 4;        // half-warp id (0/1)
    int s    = lane & 15;        // float4 column within 64-ch row
    int cA   = warp * 4 + g * 2;
    int cB   = cA + 1;

    int offA = s_off[cA],  offB = s_off[cB];
    int cntA = s_off[cA + 1] - offA;
    int cntB = s_off[cB + 1] - offB;
    int lsA  = offA - base0,  lsB = offB - base0;

    const float ninf = __int_as_float(0xff800000);
    float4 accA = make_float4(ninf, ninf, ninf, ninf);
    float4 accB = make_float4(ninf, ninf, ninf, ninf);

    if (all_staged) {
        int lo = cntA < cntB ? cntA : cntB;
        #pragma unroll 2
        for (int j = 0; j < lo; j++) {         // branch-free bulk
            int pA = s_pid[lsA + j];
            int pB = s_pid[lsB + j];
            float4 vA = x4[pA * 16 + s];
            float4 vB = x4[pB * 16 + s];
            accA.x = fmaxf(accA.x, vA.x);
            accA.y = fmaxf(accA.y, vA.y);
            accA.z = fmaxf(accA.z, vA.z);
            accA.w = fmaxf(accA.w, vA.w);
            accB.x = fmaxf(accB.x, vB.x);
            accB.y = fmaxf(accB.y, vB.y);
            accB.z = fmaxf(accB.z, vB.z);
            accB.w = fmaxf(accB.w, vB.w);
        }
        for (int j = lo; j < cntA; j++) {      // A remainder
            float4 v = x4[s_pid[lsA + j] * 16 + s];
            accA.x = fmaxf(accA.x, v.x);
            accA.y = fmaxf(accA.y, v.y);
            accA.z = fmaxf(accA.z, v.z);
            accA.w = fmaxf(accA.w, v.w);
        }
        for (int j = lo; j < cntB; j++) {      // B remainder
            float4 v = x4[s_pid[lsB + j] * 16 + s];
            accB.x = fmaxf(accB.x, v.x);
            accB.y = fmaxf(accB.y, v.y);
            accB.z = fmaxf(accB.z, v.z);
            accB.w = fmaxf(accB.w, v.w);
        }
    } else {                                    // rare fallback: global pids
        int jm = cntA > cntB ? cntA : cntB;
        for (int j = 0; j < jm; j++) {
            if (j < cntA) {
                float4 v = x4[g_pids[base0 + lsA + j] * 16 + s];
                accA.x = fmaxf(accA.x, v.x);
                accA.y = fmaxf(accA.y, v.y);
                accA.z = fmaxf(accA.z, v.z);
                accA.w = fmaxf(accA.w, v.w);
            }
            if (j < cntB) {
                float4 v = x4[g_pids[base0 + lsB + j] * 16 + s];
                accB.x = fmaxf(accB.x, v.x);
                accB.y = fmaxf(accB.y, v.y);
                accB.z = fmaxf(accB.z, v.z);
                accB.w = fmaxf(accB.w, v.w);
            }
        }
    }

    if (cntA == 0) accA = make_float4(0.f, 0.f, 0.f, 0.f);
    if (cntB == 0) accB = make_float4(0.f, 0.f, 0.f, 0.f);
    out4[(cbase + cA) * 16 + s] = accA;   // 16 lanes -> full 256B row
    out4[(cbase + cB) * 16 + s] = accB;
}

// ---------------------------------------------------------------
extern "C" void kernel_launch(void* const* d_in, const int* in_sizes, int n_in,
                              void* d_out, int out_size) {
    const float* x     = (const float*)d_in[0];
    const int2*  pos   = (const int2*)d_in[1];
    const int*   batch = (const int*)d_in[2];
    float* out = (float*)d_out;
    int n = in_sizes[2];     // number of points

    k_hist  <<<(n + 255) / 256, 256>>>(pos, batch, n);
    k_prep2 <<<PREP_BLOCKS, 1024>>>(n);
    k_gather<<<SEGS / CPB, 256>>>((const float4*)x, (float4*)out);
}

// round 13
// speedup vs baseline: 1.1250x; 1.0453x over previous
#include <cuda_runtime.h>

#define N_MAX     1048576
#define SEGS      (64 * 4096)   // 262144 segments
#define GRID_DIM  64
#define NUM_CELLS 4096
#define PREP_BLOCKS 256
#define CPB       32            // cells per gather block
#define STAGE_MAX 512           // staged pids per gather block
#define IDX_BITS  18            // SEGS = 2^18

// ---- scratch (static device globals; zero-initialized at module load) ----
__device__ int g_idx[N_MAX];           // packed: cell idx | rank<<18
__device__ int g_pids[N_MAX];          // point ids sorted by cell
__device__ int g_counts[SEGS];         // points per cell (re-zeroed in scan phase)
__device__ int g_offsets[SEGS + 1];    // exclusive prefix + sentinel
__device__ int g_blocksums[PREP_BLOCKS];
__device__ int g_prefix[PREP_BLOCKS];  // exclusive scan of block totals
// sync state (reset by k_gather block 0 for the next graph replay)
__device__ int g_d2, g_f2;             // scan publish
__device__ int g_d3, g_f3;             // scan -> scatter

// single-hop grid barrier: all blocks must be co-resident.
__device__ __forceinline__ void grid_sync(int* done, int* flag) {
    __syncthreads();
    if (threadIdx.x == 0) {
        __threadfence();
        int t = atomicAdd(done, 1);
        if (t == PREP_BLOCKS - 1) {
            atomicExch(flag, 1);
        } else {
            while (atomicAdd(flag, 0) == 0) { __nanosleep(64); }
        }
        __threadfence();
    }
    __syncthreads();
}

// ---------------------------------------------------------------
// pos/batch are int32 (JAX x64 disabled => int64 request materializes int32).
// TWO points per thread: one int4 pos load + one int2 batch load; the two
// atomic chains are independent and pipeline each other (R12 profile showed
// 1-pt/thread hist was latency-chain bound: issue 7.6%, DRAM 12%).
__global__ void k_hist2(const int2* __restrict__ pos,
                        const int* __restrict__ batch, int n) {
    int i  = blockIdx.x * blockDim.x + threadIdx.x;
    int i2 = i * 2;
    if (i2 + 1 < n) {
        int4 p = ((const int4*)pos)[i];
        int2 b = ((const int2*)batch)[i];
        int idx0 = b.x * NUM_CELLS + (p.x >> 2) * GRID_DIM + (p.y >> 2);
        int idx1 = b.y * NUM_CELLS + (p.z >> 2) * GRID_DIM + (p.w >> 2);
        int r0 = atomicAdd(&g_counts[idx0], 1);
        int r1 = atomicAdd(&g_counts[idx1], 1);
        ((int2*)g_idx)[i] = make_int2(idx0 | (r0 << IDX_BITS),
                                      idx1 | (r1 << IDX_BITS));
    } else if (i2 < n) {                      // odd tail point
        int2 p = pos[i2];
        int idx = batch[i2] * NUM_CELLS + (p.x >> 2) * GRID_DIM + (p.y >> 2);
        int r = atomicAdd(&g_counts[idx], 1);
        g_idx[i2] = idx | (r << IDX_BITS);
    }
}

// Fused scan + scatter. 256 blocks x 1024 threads, all co-resident.
__global__ void __launch_bounds__(1024) k_prep2(int n) {
    int gtid = blockIdx.x * 1024 + threadIdx.x;   // 0..262143

    // ---- scan of counts (single-hop publish) ----
    {
        int bid  = blockIdx.x;
        int i    = gtid;
        int lane = threadIdx.x & 31;
        int wid  = threadIdx.x >> 5;

        int v = g_counts[i];
        g_counts[i] = 0;                       // reset for next replay

        int incl = v;
        #pragma unroll
        for (int d = 1; d < 32; d <<= 1) {
            int u = __shfl_up_sync(0xffffffffu, incl, d);
            if (lane >= d) incl += u;
        }
        __shared__ int ws[32];
        __shared__ int wexcl[32];
        __shared__ int s_last;
        __shared__ int s_base;
        if (lane == 31) ws[wid] = incl;
        __syncthreads();
        if (wid == 0) {
            int w  = ws[lane];
            int wi = w;
            #pragma unroll
            for (int d = 1; d < 32; d <<= 1) {
                int u = __shfl_up_sync(0xffffffffu, wi, d);
                if (lane >= d) wi += u;
            }
            wexcl[lane] = wi - w;
            if (lane == 31) {
                g_blocksums[bid] = wi;         // block total
                __threadfence();
                int t = atomicAdd(&g_d2, 1);
                s_last = (t == PREP_BLOCKS - 1);
            }
        }
        __syncthreads();

        if (s_last) {                          // block-uniform branch
            __shared__ int ws2[8];
            int t = threadIdx.x;
            int bv = 0, bi = 0;
            if (t < PREP_BLOCKS) {
                bv = g_blocksums[t];
                bi = bv;
                #pragma unroll
                for (int d = 1; d < 32; d <<= 1) {
                    int u = __shfl_up_sync(0xffffffffu, bi, d);
                    if ((t & 31) >= d) bi += u;
                }
                if ((t & 31) == 31) ws2[t >> 5] = bi;
            }
            __syncthreads();
            if (t < PREP_BLOCKS) {
                int add = 0;
                #pragma unroll
                for (int wq = 0; wq < 8; wq++)
                    if (wq < (t >> 5)) add += ws2[wq];
                g_prefix[t] = bi - bv + add;   // exclusive base for block t
            }
            __syncthreads();
            if (t == 0) {
                __threadfence();
                atomicExch(&g_f2, 1);          // publish
            }
        }

        if (threadIdx.x == 0) {                // single-hop wait
            while (atomicAdd(&g_f2, 0) == 0) { __nanosleep(64); }
            __threadfence();
            s_base = g_prefix[bid];
        }
        __syncthreads();

        g_offsets[i] = incl - v + wexcl[wid] + s_base;
        if (bid == PREP_BLOCKS - 1 && threadIdx.x == 1023)
            g_offsets[SEGS] = n;               // sentinel
    }
    grid_sync(&g_d3, &g_f3);                   // all offsets visible

    // ---- atomic-free scatter ----
    #pragma unroll
    for (int k = 0; k < 4; k++) {
        int i = gtid + k * (PREP_BLOCKS * 1024);
        if (i < n) {
            int packed = g_idx[i];
            int idx  = packed & (SEGS - 1);
            int rank = ((unsigned)packed) >> IDX_BITS;
            g_pids[g_offsets[idx] + rank] = i;
        }
    }
}

// ---------------------------------------------------------------
// Gather: block = 32 contiguous cells; pids staged in smem. Half-warp
// partitioning; each lane = one float4 column, 16 lanes = full 256B row.
// Split loop: branch-free bulk over min(cntA,cntB), short predicated
// remainders. launch_bounds(256, 8): cap regs at 32 -> 2048 thr/SM (+33%
// warps vs R9's 6 blocks) to hide more of the random-row DRAM latency.
__global__ void __launch_bounds__(256, 8)
k_gather(const float4* __restrict__ x4, float4* __restrict__ out4) {
    if (blockIdx.x == 0 && threadIdx.x == 0) {
        g_d2 = 0; g_f2 = 0; g_d3 = 0; g_f3 = 0;
    }

    __shared__ int s_off[CPB + 1];
    __shared__ int s_pid[STAGE_MAX];

    int tid   = threadIdx.x;
    int cbase = blockIdx.x * CPB;

    if (tid < CPB + 1)
        s_off[tid] = g_offsets[cbase + tid];
    __syncthreads();

    int base0 = s_off[0];
    int total = s_off[CPB] - base0;
    bool all_staged = (total <= STAGE_MAX);
    int stage = all_staged ? total : 0;
    for (int i = tid; i < stage; i += 256)
        s_pid[i] = g_pids[base0 + i];
    __syncthreads();

    int warp = tid >> 5;
    int lane = tid & 31;
    int g    = lane >> 4;        // half-warp id (0/1)
    int s    = lane & 15;        // float4 column within 64-ch row
    int cA   = warp * 4 + g * 2;
    int cB   = cA + 1;

    int offA = s_off[cA],  offB = s_off[cB];
    int cntA = s_off[cA + 1] - offA;
    int cntB = s_off[cB + 1] - offB;
    int lsA  = offA - base0,  lsB = offB - base0;

    const float ninf = __int_as_float(0xff800000);
    float4 accA = make_float4(ninf, ninf, ninf, ninf);
    float4 accB = make_float4(ninf, ninf, ninf, ninf);

    if (all_staged) {
        int lo = cntA < cntB ? cntA : cntB;
        #pragma unroll 2
        for (int j = 0; j < lo; j++) {         // branch-free bulk
            int pA = s_pid[lsA + j];
            int pB = s_pid[lsB + j];
            float4 vA = x4[pA * 16 + s];
            float4 vB = x4[pB * 16 + s];
            accA.x = fmaxf(accA.x, vA.x);
            accA.y = fmaxf(accA.y, vA.y);
            accA.z = fmaxf(accA.z, vA.z);
            accA.w = fmaxf(accA.w, vA.w);
            accB.x = fmaxf(accB.x, vB.x);
            accB.y = fmaxf(accB.y, vB.y);
            accB.z = fmaxf(accB.z, vB.z);
            accB.w = fmaxf(accB.w, vB.w);
        }
        for (int j = lo; j < cntA; j++) {      // A remainder
            float4 v = x4[s_pid[lsA + j] * 16 + s];
            accA.x = fmaxf(accA.x, v.x);
            accA.y = fmaxf(accA.y, v.y);
            accA.z = fmaxf(accA.z, v.z);
            accA.w = fmaxf(accA.w, v.w);
        }
        for (int j = lo; j < cntB; j++) {      // B remainder
            float4 v = x4[s_pid[lsB + j] * 16 + s];
            accB.x = fmaxf(accB.x, v.x);
            accB.y = fmaxf(accB.y, v.y);
            accB.z = fmaxf(accB.z, v.z);
            accB.w = fmaxf(accB.w, v.w);
        }
    } else {                                    // rare fallback: global pids
        int jm = cntA > cntB ? cntA : cntB;
        for (int j = 0; j < jm; j++) {
            if (j < cntA) {
                float4 v = x4[g_pids[base0 + lsA + j] * 16 + s];
                accA.x = fmaxf(accA.x, v.x);
                accA.y = fmaxf(accA.y, v.y);
                accA.z = fmaxf(accA.z, v.z);
                accA.w = fmaxf(accA.w, v.w);
            }
            if (j < cntB) {
                float4 v = x4[g_pids[base0 + lsB + j] * 16 + s];
                accB.x = fmaxf(accB.x, v.x);
                accB.y = fmaxf(accB.y, v.y);
                accB.z = fmaxf(accB.z, v.z);
                accB.w = fmaxf(accB.w, v.w);
            }
        }
    }

    if (cntA == 0) accA = make_float4(0.f, 0.f, 0.f, 0.f);
    if (cntB == 0) accB = make_float4(0.f, 0.f, 0.f, 0.f);
    out4[(cbase + cA) * 16 + s] = accA;   // 16 lanes -> full 256B row
    out4[(cbase + cB) * 16 + s] = accB;
}

// ---------------------------------------------------------------
extern "C" void kernel_launch(void* const* d_in, const int* in_sizes, int n_in,
                              void* d_out, int out_size) {
    const float* x     = (const float*)d_in[0];
    const int2*  pos   = (const int2*)d_in[1];
    const int*   batch = (const int*)d_in[2];
    float* out = (float*)d_out;
    int n = in_sizes[2];     // number of points

    int nhalf = (n + 1) / 2;
    k_hist2 <<<(nhalf + 255) / 256, 256>>>(pos, batch, n);
    k_prep2 <<<PREP_BLOCKS, 1024>>>(n);
    k_gather<<<SEGS / CPB, 256>>>((const float4*)x, (float4*)out);
}

// round 14
// speedup vs baseline: 1.2295x; 1.0929x over previous
#include <cuda_runtime.h>

#define N_MAX     1048576
#define SEGS      (64 * 4096)   // 262144 segments
#define NB        64            // batches
#define GRID_DIM  64
#define NUM_CELLS 4096
#define CPB       32            // cells per gather block
#define STAGE_MAX 512           // staged pids per gather block

// ---- scratch (static device globals; no persistent state across replays —
//      every entry is rewritten on every call) ----
__device__ int g_pids[N_MAX];          // point ids grouped by cell
__device__ int g_offsets[SEGS + 1];    // exclusive prefix + sentinel
__device__ int g_bstart[NB + 1];       // first point index of each batch

// ---------------------------------------------------------------
// batch is SORTED (int32; JAX x64 disabled => int64 request materializes
// int32). Mark transitions to get per-batch ranges.
__global__ void k_bounds(const int* __restrict__ batch, int n) {
    int i = blockIdx.x * blockDim.x + threadIdx.x;
    if (i >= n) return;
    int b = batch[i];
    if (i == 0) {
        for (int q = 0; q <= b; q++) g_bstart[q] = 0;
    } else {
        int pb = batch[i - 1];
        for (int q = pb + 1; q <= b; q++) g_bstart[q] = i;
    }
    if (i == n - 1) {
        for (int q = b + 1; q <= NB; q++) g_bstart[q] = n;
    }
}

// One block per batch: hist + scan + scatter fully in SMEM (zero global
// atomics, zero cross-block sync). Key invariant: cell ids are batch-major,
// so batch b's global offset base is exactly g_bstart[b].
__global__ void __launch_bounds__(1024) k_prep_batch(const int2* __restrict__ pos,
                                                     int n) {
    __shared__ __align__(16) int s_cnt[NUM_CELLS];   // counts -> excl -> cursors
    __shared__ int ws[32], wexcl[32];

    int b    = blockIdx.x;
    int tid  = threadIdx.x;
    int lane = tid & 31;
    int wid  = tid >> 5;
    int lo   = g_bstart[b];
    int hi   = g_bstart[b + 1];

    // zero counters
    ((int4*)s_cnt)[tid] = make_int4(0, 0, 0, 0);
    __syncthreads();

    // pass 1: smem histogram (batch known == b inside [lo,hi))
    for (int i = lo + tid; i < hi; i += 1024) {
        int2 p = pos[i];
        int c = (p.x >> 2) * GRID_DIM + (p.y >> 2);
        atomicAdd(&s_cnt[c], 1);
    }
    __syncthreads();

    // in-block exclusive scan of 4096 counters (4 per thread)
    int4 c4 = ((int4*)s_cnt)[tid];
    int sum = c4.x + c4.y + c4.z + c4.w;
    int incl = sum;
    #pragma unroll
    for (int d = 1; d < 32; d <<= 1) {
        int u = __shfl_up_sync(0xffffffffu, incl, d);
        if (lane >= d) incl += u;
    }
    if (lane == 31) ws[wid] = incl;
    __syncthreads();
    if (wid == 0) {
        int w = ws[lane];
        int wi = w;
        #pragma unroll
        for (int d = 1; d < 32; d <<= 1) {
            int u = __shfl_up_sync(0xffffffffu, wi, d);
            if (lane >= d) wi += u;
        }
        wexcl[lane] = wi - w;
    }
    __syncthreads();
    int e0 = incl - sum + wexcl[wid];          // exclusive base of element 4*tid
    int e1 = e0 + c4.x;
    int e2 = e1 + c4.y;
    int e3 = e2 + c4.z;
    ((int4*)s_cnt)[tid] = make_int4(e0, e1, e2, e3);   // now cursors

    // publish global offsets (cells of batch b start at global slot lo)
    int obase = b * NUM_CELLS + tid * 4;
    ((int4*)&g_offsets[obase])[0] = make_int4(lo + e0, lo + e1, lo + e2, lo + e3);
    if (b == NB - 1 && tid == 1023)
        g_offsets[SEGS] = n;                   // sentinel
    __syncthreads();

    // pass 2: place pids via smem cursors (pos re-read is L2-hot)
    for (int i = lo + tid; i < hi; i += 1024) {
        int2 p = pos[i];
        int c = (p.x >> 2) * GRID_DIM + (p.y >> 2);
        int r = atomicAdd(&s_cnt[c], 1);       // local slot within batch
        g_pids[lo + r] = i;
    }
}

// ---------------------------------------------------------------
// Gather (R13 winner, unchanged): block = 32 contiguous cells; pids staged in
// smem. Half-warp partitioning; each lane = one float4 column, 16 lanes =
// full 256B row. Split loop: branch-free bulk over min(cntA,cntB), short
// predicated remainders. launch_bounds(256, 8) -> 2048 thr/SM.
__global__ void __launch_bounds__(256, 8)
k_gather(const float4* __restrict__ x4, float4* __restrict__ out4) {
    __shared__ int s_off[CPB + 1];
    __shared__ int s_pid[STAGE_MAX];

    int tid   = threadIdx.x;
    int cbase = blockIdx.x * CPB;

    if (tid < CPB + 1)
        s_off[tid] = g_offsets[cbase + tid];
    __syncthreads();

    int base0 = s_off[0];
    int total = s_off[CPB] - base0;
    bool all_staged = (total <= STAGE_MAX);
    int stage = all_staged ? total : 0;
    for (int i = tid; i < stage; i += 256)
        s_pid[i] = g_pids[base0 + i];
    __syncthreads();

    int warp = tid >> 5;
    int lane = tid & 31;
    int g    = lane >> 4;        // half-warp id (0/1)
    int s    = lane & 15;        // float4 column within 64-ch row
    int cA   = warp * 4 + g * 2;
    int cB   = cA + 1;

    int offA = s_off[cA],  offB = s_off[cB];
    int cntA = s_off[cA + 1] - offA;
    int cntB = s_off[cB + 1] - offB;
    int lsA  = offA - base0,  lsB = offB - base0;

    const float ninf = __int_as_float(0xff800000);
    float4 accA = make_float4(ninf, ninf, ninf, ninf);
    float4 accB = make_float4(ninf, ninf, ninf, ninf);

    if (all_staged) {
        int lo = cntA < cntB ? cntA : cntB;
        #pragma unroll 2
        for (int j = 0; j < lo; j++) {         // branch-free bulk
            int pA = s_pid[lsA + j];
            int pB = s_pid[lsB + j];
            float4 vA = x4[pA * 16 + s];
            float4 vB = x4[pB * 16 + s];
            accA.x = fmaxf(accA.x, vA.x);
            accA.y = fmaxf(accA.y, vA.y);
            accA.z = fmaxf(accA.z, vA.z);
            accA.w = fmaxf(accA.w, vA.w);
            accB.x = fmaxf(accB.x, vB.x);
            accB.y = fmaxf(accB.y, vB.y);
            accB.z = fmaxf(accB.z, vB.z);
            accB.w = fmaxf(accB.w, vB.w);
        }
        for (int j = lo; j < cntA; j++) {      // A remainder
            float4 v = x4[s_pid[lsA + j] * 16 + s];
            accA.x = fmaxf(accA.x, v.x);
            accA.y = fmaxf(accA.y, v.y);
            accA.z = fmaxf(accA.z, v.z);
            accA.w = fmaxf(accA.w, v.w);
        }
        for (int j = lo; j < cntB; j++) {      // B remainder
            float4 v = x4[s_pid[lsB + j] * 16 + s];
            accB.x = fmaxf(accB.x, v.x);
            accB.y = fmaxf(accB.y, v.y);
            accB.z = fmaxf(accB.z, v.z);
            accB.w = fmaxf(accB.w, v.w);
        }
    } else {                                    // rare fallback: global pids
        int jm = cntA > cntB ? cntA : cntB;
        for (int j = 0; j < jm; j++) {
            if (j < cntA) {
                float4 v = x4[g_pids[base0 + lsA + j] * 16 + s];
                accA.x = fmaxf(accA.x, v.x);
                accA.y = fmaxf(accA.y, v.y);
                accA.z = fmaxf(accA.z, v.z);
                accA.w = fmaxf(accA.w, v.w);
            }
            if (j < cntB) {
                float4 v = x4[g_pids[base0 + lsB + j] * 16 + s];
                accB.x = fmaxf(accB.x, v.x);
                accB.y = fmaxf(accB.y, v.y);
                accB.z = fmaxf(accB.z, v.z);
                accB.w = fmaxf(accB.w, v.w);
            }
        }
    }

    if (cntA == 0) accA = make_float4(0.f, 0.f, 0.f, 0.f);
    if (cntB == 0) accB = make_float4(0.f, 0.f, 0.f, 0.f);
    out4[(cbase + cA) * 16 + s] = accA;   // 16 lanes -> full 256B row
    out4[(cbase + cB) * 16 + s] = accB;
}

// ---------------------------------------------------------------
extern "C" void kernel_launch(void* const* d_in, const int* in_sizes, int n_in,
                              void* d_out, int out_size) {
    const float* x     = (const float*)d_in[0];
    const int2*  pos   = (const int2*)d_in[1];
    const int*   batch = (const int*)d_in[2];
    float* out = (float*)d_out;
    int n = in_sizes[2];     // number of points

    k_bounds    <<<(n + 1023) / 1024, 1024>>>(batch, n);
    k_prep_batch<<<NB, 1024>>>(pos, n);
    k_gather    <<<SEGS / CPB, 256>>>((const float4*)x, (float4*)out);
}

// round 15
// speedup vs baseline: 1.3044x; 1.0609x over previous
#include <cuda_runtime.h>

#define N_MAX     1048576
#define SEGS      (64 * 4096)   // 262144 segments
#define NB        64            // batches
#define GRID_DIM  64
#define NUM_CELLS 4096
#define SPLIT     4             // blocks per batch in prep
#define CPB       32            // cells per gather block
#define STAGE_MAX 512           // staged pids per gather block

// ---- scratch (static device globals) ----
__device__ int g_pids[N_MAX];            // point ids grouped by cell
__device__ int g_offsets[SEGS + 1];      // exclusive prefix + sentinel
__device__ int g_bstart[NB + 1];         // first point index of each batch
__device__ int g_hcnt[SPLIT][SEGS];      // per-split per-cell counts
__device__ int g_sync[NB];               // per-batch arrival ctr (reset by gather)

// ---------------------------------------------------------------
// batch is SORTED int32 (JAX x64 disabled => int64 request materializes
// int32). int4-vectorized transition marking.
__global__ void k_bounds(const int* __restrict__ batch, int n) {
    int i  = blockIdx.x * blockDim.x + threadIdx.x;
    int i4 = i * 4;
    if (i4 >= n) return;
    int4 v = ((const int4*)batch)[i];
    int prev = (i4 == 0) ? -1 : batch[i4 - 1];
    if (prev != v.x) for (int q = prev + 1; q <= v.x; q++) g_bstart[q] = i4;
    if (v.x != v.y)  for (int q = v.x + 1;  q <= v.y; q++) g_bstart[q] = i4 + 1;
    if (v.y != v.z)  for (int q = v.y + 1;  q <= v.z; q++) g_bstart[q] = i4 + 2;
    if (v.z != v.w)  for (int q = v.z + 1;  q <= v.w; q++) g_bstart[q] = i4 + 3;
    if (i4 + 4 >= n) for (int q = v.w + 1;  q <= NB;  q++) g_bstart[q] = n;
}

// 4 blocks per batch, each owning a quarter of the batch's points.
// smem histogram -> publish counts -> single-hop sibling sync -> absolute
// cursors (lo + excl_scan(total) + prefix over earlier splits) -> atomic-free
// (vs other blocks) scatter of own quarter. 256 blocks: full chip.
__global__ void __launch_bounds__(1024) k_prep_split(const int2* __restrict__ pos,
                                                     int n) {
    __shared__ __align__(16) int s_cnt[NUM_CELLS];   // counts -> cursors
    __shared__ int ws[32], wexcl[32];

    int bk   = blockIdx.x;
    int b    = bk >> 2;
    int k    = bk & 3;
    int tid  = threadIdx.x;
    int lane = tid & 31;
    int wid  = tid >> 5;

    int lo   = g_bstart[b];
    int hi   = g_bstart[b + 1];
    int len  = hi - lo;
    int qlen = (len + SPLIT - 1) / SPLIT;
    int plo  = lo + k * qlen;
    int phi  = plo + qlen < hi ? plo + qlen : hi;
    if (phi < plo) phi = plo;

    ((int4*)s_cnt)[tid] = make_int4(0, 0, 0, 0);
    __syncthreads();

    // pass 1: smem histogram of my quarter
    for (int i = plo + tid; i < phi; i += 1024) {
        int2 p = pos[i];
        int c = (p.x >> 2) * GRID_DIM + (p.y >> 2);
        atomicAdd(&s_cnt[c], 1);
    }
    __syncthreads();

    // publish my counts; arrive
    int4 mine = ((int4*)s_cnt)[tid];
    ((int4*)&g_hcnt[k][b * NUM_CELLS])[tid] = mine;
    __threadfence();
    if (tid == 0) {
        atomicAdd(&g_sync[b], 1);
        while (atomicAdd(&g_sync[b], 0) < SPLIT) { __nanosleep(40); }
        __threadfence();
    }
    __syncthreads();

    // combine all splits: tot = sum_j cnt_j, pre = sum_{j<k} cnt_j
    int4 tot = mine;
    int4 pre = make_int4(0, 0, 0, 0);
    #pragma unroll
    for (int j = 0; j < SPLIT; j++) {
        if (j == k) continue;
        int4 o = ((const int4*)&g_hcnt[j][b * NUM_CELLS])[tid];
        tot.x += o.x; tot.y += o.y; tot.z += o.z; tot.w += o.w;
        if (j < k) { pre.x += o.x; pre.y += o.y; pre.z += o.z; pre.w += o.w; }
    }

    // block scan of per-thread totals (4 cells/thread)
    int sum  = tot.x + tot.y + tot.z + tot.w;
    int incl = sum;
    #pragma unroll
    for (int d = 1; d < 32; d <<= 1) {
        int u = __shfl_up_sync(0xffffffffu, incl, d);
        if (lane >= d) incl += u;
    }
    if (lane == 31) ws[wid] = incl;
    __syncthreads();
    if (wid == 0) {
        int w = ws[lane];
        int wi = w;
        #pragma unroll
        for (int d = 1; d < 32; d <<= 1) {
            int u = __shfl_up_sync(0xffffffffu, wi, d);
            if (lane >= d) wi += u;
        }
        wexcl[lane] = wi - w;
    }
    __syncthreads();
    int e0 = incl - sum + wexcl[wid];      // excl base of cell 4*tid (in batch)
    int e1 = e0 + tot.x;
    int e2 = e1 + tot.y;
    int e3 = e2 + tot.z;

    // my absolute cursors
    ((int4*)s_cnt)[tid] = make_int4(lo + e0 + pre.x, lo + e1 + pre.y,
                                    lo + e2 + pre.z, lo + e3 + pre.w);
    // global offsets: written once (split 0)
    if (k == 0) {
        ((int4*)&g_offsets[b * NUM_CELLS])[tid] =
            make_int4(lo + e0, lo + e1, lo + e2, lo + e3);
        if (b == NB - 1 && tid == 1023)
            g_offsets[SEGS] = n;           // sentinel
    }
    __syncthreads();

    // pass 2: place my quarter's pids (pos re-read is L2-hot)
    for (int i = plo + tid; i < phi; i += 1024) {
        int2 p = pos[i];
        int c = (p.x >> 2) * GRID_DIM + (p.y >> 2);
        int r = atomicAdd(&s_cnt[c], 1);   // absolute slot
        g_pids[r] = i;
    }
}

// ---------------------------------------------------------------
// Gather (R13/R14 winner, unchanged): block = 32 contiguous cells; pids
// staged in smem. Half-warp partitioning; each lane = one float4 column, 16
// lanes = full 256B row. Split loop: branch-free bulk over min(cntA,cntB),
// short predicated remainders. launch_bounds(256, 8) -> 2048 thr/SM.
// Runs at ~5.2TB/s effective (~83% of measured LTS cap) — near ceiling.
__global__ void __launch_bounds__(256, 8)
k_gather(const float4* __restrict__ x4, float4* __restrict__ out4) {
    if (blockIdx.x == 0 && threadIdx.x < NB)
        g_sync[threadIdx.x] = 0;           // reset prep sync for next replay

    __shared__ int s_off[CPB + 1];
    __shared__ int s_pid[STAGE_MAX];

    int tid   = threadIdx.x;
    int cbase = blockIdx.x * CPB;

    if (tid < CPB + 1)
        s_off[tid] = g_offsets[cbase + tid];
    __syncthreads();

    int base0 = s_off[0];
    int total = s_off[CPB] - base0;
    bool all_staged = (total <= STAGE_MAX);
    int stage = all_staged ? total : 0;
    for (int i = tid; i < stage; i += 256)
        s_pid[i] = g_pids[base0 + i];
    __syncthreads();

    int warp = tid >> 5;
    int lane = tid & 31;
    int g    = lane >> 4;        // half-warp id (0/1)
    int s    = lane & 15;        // float4 column within 64-ch row
    int cA   = warp * 4 + g * 2;
    int cB   = cA + 1;

    int offA = s_off[cA],  offB = s_off[cB];
    int cntA = s_off[cA + 1] - offA;
    int cntB = s_off[cB + 1] - offB;
    int lsA  = offA - base0,  lsB = offB - base0;

    const float ninf = __int_as_float(0xff800000);
    float4 accA = make_float4(ninf, ninf, ninf, ninf);
    float4 accB = make_float4(ninf, ninf, ninf, ninf);

    if (all_staged) {
        int lo = cntA < cntB ? cntA : cntB;
        #pragma unroll 2
        for (int j = 0; j < lo; j++) {         // branch-free bulk
            int pA = s_pid[lsA + j];
            int pB = s_pid[lsB + j];
            float4 vA = x4[pA * 16 + s];
            float4 vB = x4[pB * 16 + s];
            accA.x = fmaxf(accA.x, vA.x);
            accA.y = fmaxf(accA.y, vA.y);
            accA.z = fmaxf(accA.z, vA.z);
            accA.w = fmaxf(accA.w, vA.w);
            accB.x = fmaxf(accB.x, vB.x);
            accB.y = fmaxf(accB.y, vB.y);
            accB.z = fmaxf(accB.z, vB.z);
            accB.w = fmaxf(accB.w, vB.w);
        }
        for (int j = lo; j < cntA; j++) {      // A remainder
            float4 v = x4[s_pid[lsA + j] * 16 + s];
            accA.x = fmaxf(accA.x, v.x);
            accA.y = fmaxf(accA.y, v.y);
            accA.z = fmaxf(accA.z, v.z);
            accA.w = fmaxf(accA.w, v.w);
        }
        for (int j = lo; j < cntB; j++) {      // B remainder
            float4 v = x4[s_pid[lsB + j] * 16 + s];
            accB.x = fmaxf(accB.x, v.x);
            accB.y = fmaxf(accB.y, v.y);
            accB.z = fmaxf(accB.z, v.z);
            accB.w = fmaxf(accB.w, v.w);
        }
    } else {                                    // rare fallback: global pids
        int jm = cntA > cntB ? cntA : cntB;
        for (int j = 0; j < jm; j++) {
            if (j < cntA) {
                float4 v = x4[g_pids[base0 + lsA + j] * 16 + s];
                accA.x = fmaxf(accA.x, v.x);
                accA.y = fmaxf(accA.y, v.y);
                accA.z = fmaxf(accA.z, v.z);
                accA.w = fmaxf(accA.w, v.w);
            }
            if (j < cntB) {
                float4 v = x4[g_pids[base0 + lsB + j] * 16 + s];
                accB.x = fmaxf(accB.x, v.x);
                accB.y = fmaxf(accB.y, v.y);
                accB.z = fmaxf(accB.z, v.z);
                accB.w = fmaxf(accB.w, v.w);
            }
        }
    }

    if (cntA == 0) accA = make_float4(0.f, 0.f, 0.f, 0.f);
    if (cntB == 0) accB = make_float4(0.f, 0.f, 0.f, 0.f);
    out4[(cbase + cA) * 16 + s] = accA;   // 16 lanes -> full 256B row
    out4[(cbase + cB) * 16 + s] = accB;
}

// ---------------------------------------------------------------
extern "C" void kernel_launch(void* const* d_in, const int* in_sizes, int n_in,
                              void* d_out, int out_size) {
    const float* x     = (const float*)d_in[0];
    const int2*  pos   = (const int2*)d_in[1];
    const int*   batch = (const int*)d_in[2];
    float* out = (float*)d_out;
    int n = in_sizes[2];     // number of points

    int n4 = (n + 3) / 4;
    k_bounds    <<<(n4 + 255) / 256, 256>>>(batch, n);
    k_prep_split<<<NB * SPLIT, 1024>>>(pos, n);
    k_gather    <<<SEGS / CPB, 256>>>((const float4*)x, (float4*)out);
}

// round 16
// speedup vs baseline: 1.3267x; 1.0171x over previous
#include <cuda_runtime.h>

#define N_MAX     1048576
#define SEGS      (64 * 4096)   // 262144 segments
#define NB        64            // batches
#define GRID_DIM  64
#define NUM_CELLS 4096
#define SPLIT     4             // blocks per batch in prep
#define CPB       32            // cells per gather block
#define STAGE_MAX 512           // staged pids per gather block
#define CCACHE    6             // cell ids cached in regs per thread

// ---- scratch (static device globals) ----
__device__ int g_pids[N_MAX];            // point ids grouped by cell
__device__ int g_offsets[SEGS + 1];      // exclusive prefix + sentinel
__device__ int g_hcnt[SPLIT][SEGS];      // per-split per-cell counts
__device__ int g_sync[NB];               // per-batch arrival ctr (reset by gather)

// warp-collective 32-ary lower_bound over sorted int array:
// returns smallest i with a[i] >= tgt (n if none). ~4 probe rounds for n=1M.
__device__ __forceinline__ int lower_bound32(const int* __restrict__ a, int n,
                                             int tgt) {
    int lane = threadIdx.x & 31;
    int lo = -1, hi = n;                 // invariant: a[lo] < tgt <= a[hi]
    while (hi - lo > 1) {
        int span = hi - lo;              // >= 2
        int step = (span + 32) / 33;     // >= 1
        int p = lo + (lane + 1) * step;
        bool ge = (p >= hi) ? true : (a[p] >= tgt);
        unsigned m = __ballot_sync(0xffffffffu, ge);
        if (m == 0) {
            lo += 32 * step;             // all probes < tgt
        } else {
            int k = __ffs(m) - 1;        // first probe with a[p] >= tgt
            int nh = lo + (k + 1) * step; if (nh > hi) nh = hi;
            lo = lo + k * step;          // a[new lo] < tgt (k==0 -> unchanged)
            hi = nh;
        }
    }
    return hi;
}

// ---------------------------------------------------------------
// 4 blocks per batch, each owning a quarter of the batch's points.
// Batch bounds found in-kernel via warp 32-ary search (batch is SORTED int32;
// JAX x64 disabled => int64 request materializes int32). smem histogram with
// cell ids CACHED IN REGISTERS -> publish counts -> single-hop sibling sync ->
// absolute cursors -> scatter own quarter (no pos re-read). 256 blocks.
__global__ void __launch_bounds__(1024) k_prep(const int2* __restrict__ pos,
                                               const int* __restrict__ batch,
                                               int n) {
    __shared__ __align__(16) int s_cnt[NUM_CELLS];   // counts -> cursors
    __shared__ int ws[32], wexcl[32];
    __shared__ int s_lo, s_hi;

    int bk   = blockIdx.x;
    int b    = bk >> 2;
    int k    = bk & 3;
    int tid  = threadIdx.x;
    int lane = tid & 31;
    int wid  = tid >> 5;

    // zero counters (all threads), then warps 0/1 search the batch bounds
    ((int4*)s_cnt)[tid] = make_int4(0, 0, 0, 0);
    if (wid == 0) {
        int r = lower_bound32(batch, n, b);
        if (lane == 0) s_lo = r;
    } else if (wid == 1) {
        int r = lower_bound32(batch, n, b + 1);
        if (lane == 0) s_hi = r;
    }
    __syncthreads();

    int lo   = s_lo;
    int hi   = s_hi;
    int len  = hi - lo;
    int qlen = (len + SPLIT - 1) / SPLIT;
    int plo  = lo + k * qlen;
    int phi  = plo + qlen < hi ? plo + qlen : hi;
    if (phi < plo) phi = plo;

    // pass 1: smem histogram of my quarter; cache cell ids in registers
    int cc[CCACHE];
    #pragma unroll
    for (int t = 0; t < CCACHE; t++) cc[t] = -1;
    int i = plo + tid;
    #pragma unroll
    for (int t = 0; t < CCACHE; t++) {
        if (i < phi) {
            int2 p = pos[i];
            int c = (p.x >> 2) * GRID_DIM + (p.y >> 2);
            cc[t] = c;
            atomicAdd(&s_cnt[c], 1);
            i += 1024;
        }
    }
    for (; i < phi; i += 1024) {             // fallback (statistically never)
        int2 p = pos[i];
        atomicAdd(&s_cnt[(p.x >> 2) * GRID_DIM + (p.y >> 2)], 1);
    }
    __syncthreads();

    // publish my counts; single-hop sibling sync (4 blocks per batch)
    int4 mine = ((int4*)s_cnt)[tid];
    ((int4*)&g_hcnt[k][b * NUM_CELLS])[tid] = mine;
    __threadfence();
    if (tid == 0) {
        atomicAdd(&g_sync[b], 1);
        while (atomicAdd(&g_sync[b], 0) < SPLIT) { __nanosleep(40); }
        __threadfence();
    }
    __syncthreads();

    // combine splits: tot = sum_j cnt_j, pre = sum_{j<k} cnt_j
    int4 tot = mine;
    int4 pre = make_int4(0, 0, 0, 0);
    #pragma unroll
    for (int j = 0; j < SPLIT; j++) {
        if (j == k) continue;
        int4 o = ((const int4*)&g_hcnt[j][b * NUM_CELLS])[tid];
        tot.x += o.x; tot.y += o.y; tot.z += o.z; tot.w += o.w;
        if (j < k) { pre.x += o.x; pre.y += o.y; pre.z += o.z; pre.w += o.w; }
    }

    // block scan of per-thread totals (4 cells/thread)
    int sum  = tot.x + tot.y + tot.z + tot.w;
    int incl = sum;
    #pragma unroll
    for (int d = 1; d < 32; d <<= 1) {
        int u = __shfl_up_sync(0xffffffffu, incl, d);
        if (lane >= d) incl += u;
    }
    if (lane == 31) ws[wid] = incl;
    __syncthreads();
    if (wid == 0) {
        int w = ws[lane];
        int wi = w;
        #pragma unroll
        for (int d = 1; d < 32; d <<= 1) {
            int u = __shfl_up_sync(0xffffffffu, wi, d);
            if (lane >= d) wi += u;
        }
        wexcl[lane] = wi - w;
    }
    __syncthreads();
    int e0 = incl - sum + wexcl[wid];      // excl base of cell 4*tid (in batch)
    int e1 = e0 + tot.x;
    int e2 = e1 + tot.y;
    int e3 = e2 + tot.z;

    // my absolute cursors
    ((int4*)s_cnt)[tid] = make_int4(lo + e0 + pre.x, lo + e1 + pre.y,
                                    lo + e2 + pre.z, lo + e3 + pre.w);
    // global offsets written once per batch (split 0)
    if (k == 0) {
        ((int4*)&g_offsets[b * NUM_CELLS])[tid] =
            make_int4(lo + e0, lo + e1, lo + e2, lo + e3);
        if (b == NB - 1 && tid == 1023)
            g_offsets[SEGS] = n;           // sentinel
    }
    __syncthreads();

    // pass 2: place pids using the CACHED cell ids (no pos re-read)
    i = plo + tid;
    #pragma unroll
    for (int t = 0; t < CCACHE; t++) {
        if (cc[t] >= 0) {
            int r = atomicAdd(&s_cnt[cc[t]], 1);   // absolute slot
            g_pids[r] = i;
            i += 1024;
        }
    }
    for (; i < phi; i += 1024) {             // fallback (matches pass-1 order)
        int2 p = pos[i];
        int c = (p.x >> 2) * GRID_DIM + (p.y >> 2);
        int r = atomicAdd(&s_cnt[c], 1);
        g_pids[r] = i;
    }
}

// ---------------------------------------------------------------
// Gather (R13-R15 winner, unchanged): block = 32 contiguous cells; pids
// staged in smem. Half-warp partitioning; each lane = one float4 column, 16
// lanes = full 256B row. Split loop: branch-free bulk over min(cntA,cntB),
// short predicated remainders. launch_bounds(256, 8) -> 2048 thr/SM.
// ~5.2TB/s effective — near the random-row DRAM ceiling; do not touch.
__global__ void __launch_bounds__(256, 8)
k_gather(const float4* __restrict__ x4, float4* __restrict__ out4) {
    if (blockIdx.x == 0 && threadIdx.x < NB)
        g_sync[threadIdx.x] = 0;           // reset prep sync for next replay

    __shared__ int s_off[CPB + 1];
    __shared__ int s_pid[STAGE_MAX];

    int tid   = threadIdx.x;
    int cbase = blockIdx.x * CPB;

    if (tid < CPB + 1)
        s_off[tid] = g_offsets[cbase + tid];
    __syncthreads();

    int base0 = s_off[0];
    int total = s_off[CPB] - base0;
    bool all_staged = (total <= STAGE_MAX);
    int stage = all_staged ? total : 0;
    for (int i = tid; i < stage; i += 256)
        s_pid[i] = g_pids[base0 + i];
    __syncthreads();

    int warp = tid >> 5;
    int lane = tid & 31;
    int g    = lane >> 4;        // half-warp id (0/1)
    int s    = lane & 15;        // float4 column within 64-ch row
    int cA   = warp * 4 + g * 2;
    int cB   = cA + 1;

    int offA = s_off[cA],  offB = s_off[cB];
    int cntA = s_off[cA + 1] - offA;
    int cntB = s_off[cB + 1] - offB;
    int lsA  = offA - base0,  lsB = offB - base0;

    const float ninf = __int_as_float(0xff800000);
    float4 accA = make_float4(ninf, ninf, ninf, ninf);
    float4 accB = make_float4(ninf, ninf, ninf, ninf);

    if (all_staged) {
        int lo = cntA < cntB ? cntA : cntB;
        #pragma unroll 2
        for (int j = 0; j < lo; j++) {         // branch-free bulk
            int pA = s_pid[lsA + j];
            int pB = s_pid[lsB + j];
            float4 vA = x4[pA * 16 + s];
            float4 vB = x4[pB * 16 + s];
            accA.x = fmaxf(accA.x, vA.x);
            accA.y = fmaxf(accA.y, vA.y);
            accA.z = fmaxf(accA.z, vA.z);
            accA.w = fmaxf(accA.w, vA.w);
            accB.x = fmaxf(accB.x, vB.x);
            accB.y = fmaxf(accB.y, vB.y);
            accB.z = fmaxf(accB.z, vB.z);
            accB.w = fmaxf(accB.w, vB.w);
        }
        for (int j = lo; j < cntA; j++) {      // A remainder
            float4 v = x4[s_pid[lsA + j] * 16 + s];
            accA.x = fmaxf(accA.x, v.x);
            accA.y = fmaxf(accA.y, v.y);
            accA.z = fmaxf(accA.z, v.z);
            accA.w = fmaxf(accA.w, v.w);
        }
        for (int j = lo; j < cntB; j++) {      // B remainder
            float4 v = x4[s_pid[lsB + j] * 16 + s];
            accB.x = fmaxf(accB.x, v.x);
            accB.y = fmaxf(accB.y, v.y);
            accB.z = fmaxf(accB.z, v.z);
            accB.w = fmaxf(accB.w, v.w);
        }
    } else {                                    // rare fallback: global pids
        int jm = cntA > cntB ? cntA : cntB;
        for (int j = 0; j < jm; j++) {
            if (j < cntA) {
                float4 v = x4[g_pids[base0 + lsA + j] * 16 + s];
                accA.x = fmaxf(accA.x, v.x);
                accA.y = fmaxf(accA.y, v.y);
                accA.z = fmaxf(accA.z, v.z);
                accA.w = fmaxf(accA.w, v.w);
            }
            if (j < cntB) {
                float4 v = x4[g_pids[base0 + lsB + j] * 16 + s];
                accB.x = fmaxf(accB.x, v.x);
                accB.y = fmaxf(accB.y, v.y);
                accB.z = fmaxf(accB.z, v.z);
                accB.w = fmaxf(accB.w, v.w);
            }
        }
    }

    if (cntA == 0) accA = make_float4(0.f, 0.f, 0.f, 0.f);
    if (cntB == 0) accB = make_float4(0.f, 0.f, 0.f, 0.f);
    out4[(cbase + cA) * 16 + s] = accA;   // 16 lanes -> full 256B row
    out4[(cbase + cB) * 16 + s] = accB;
}

// ---------------------------------------------------------------
extern "C" void kernel_launch(void* const* d_in, const int* in_sizes, int n_in,
                              void* d_out, int out_size) {
    const float* x     = (const float*)d_in[0];
    const int2*  pos   = (const int2*)d_in[1];
    const int*   batch = (const int*)d_in[2];
    float* out = (float*)d_out;
    int n = in_sizes[2];     // number of points

    k_prep  <<<NB * SPLIT, 1024>>>(pos, batch, n);
    k_gather<<<SEGS / CPB, 256>>>((const float4*)x, (float4*)out);
}